// round 15
// baseline (speedup 1.0000x reference)
#include <cuda_runtime.h>
#include <stdint.h>

// ---------------- level geometry (verified: sum of sizes == 5262476) ----------------
#define NLVL 16

static __device__ __forceinline__ constexpr int RES_(int l) {
    constexpr int r[16] = {16,20,25,32,40,50,64,80,101,128,161,203,256,322,406,512};
    return r[l];
}
static __device__ __forceinline__ constexpr int OFF_(int l) {
    constexpr int o[16] = {0,4913,14174,31750,67687,136608,269259,543884,
                           1068172,1592460,2116748,2641036,3165324,3689612,4213900,4738188};
    return o[l];
}
static __device__ __forceinline__ constexpr int DSIZE_(int l) {
    constexpr int s[7] = {4913,9261,17576,35937,68921,132651,274625};
    return s[l];
}
#define DTOTAL 543884
#define NBLK_A ((DTOTAL + 255) / 256)

// De-hashed dense z-pair tables for levels 0..6 ONLY (L7/L8 spatial tables
// tried in R8/R9: extra L2 footprint cancelled their savings — reverted).
__device__ float4 g_densep[DTOTAL];

// ---------------- sort scratch ----------------
#define NB   262144             // 64^3 morton buckets
#define MAXB (1 << 20)
__device__ int    g_hist[NB + 1];   // [NB] = global base counter; zero-init at load,
                                    // re-zeroed by the main kernel each run
__device__ float4 g_sorted[MAXB];   // {x, y, z, bitcast(orig_idx)}

// ---------------- morton bucketing (6 bits/dim -> 64^3 buckets) ----------------
__device__ __forceinline__ unsigned spread3(unsigned v) {
    v &= 0x3Fu;
    v = (v | (v << 8)) & 0x0300F00Fu;
    v = (v | (v << 4)) & 0x030C30C3u;
    v = (v | (v << 2)) & 0x09249249u;
    return v;
}
__device__ __forceinline__ int bucket_of(float px, float py, float pz) {
    float nx = (px + 0.75f) * (1.0f / 1.5f);
    float ny = (py + 0.75f) * (1.0f / 1.5f);
    float nz = (pz + 0.75f) * (1.0f / 1.5f);
    int cx = (int)(nx * 64.0f); cx = cx < 0 ? 0 : (cx > 63 ? 63 : cx);
    int cy = (int)(ny * 64.0f); cy = cy < 0 ? 0 : (cy > 63 ? 63 : cy);
    int cz = (int)(nz * 64.0f); cz = cz < 0 ? 0 : (cz > 63 ? 63 : cz);
    return (int)(spread3((unsigned)cx) | (spread3((unsigned)cy) << 1)
               | (spread3((unsigned)cz) << 2));
}

// decode 4 points from 3 float4 vector loads (base point index i0, i0 % 4 == 0)
__device__ __forceinline__ void load4pts(const float4* __restrict__ x4, int i0,
                                         float3& p0, float3& p1, float3& p2, float3& p3) {
    int f = (i0 * 3) >> 2;
    float4 v0 = x4[f], v1 = x4[f + 1], v2 = x4[f + 2];
    p0 = make_float3(v0.x, v0.y, v0.z);
    p1 = make_float3(v0.w, v1.x, v1.y);
    p2 = make_float3(v1.z, v1.w, v2.x);
    p3 = make_float3(v2.y, v2.z, v2.w);
}

// ---------------- kernel 1: key histogram (4 points/thread) ----------------
__global__ void __launch_bounds__(256) keyhist_kernel(const float* __restrict__ xyz, int B) {
    int i0 = (blockIdx.x * 256 + threadIdx.x) * 4;
    if (i0 + 3 < B) {
        float3 p0, p1, p2, p3;
        load4pts((const float4*)xyz, i0, p0, p1, p2, p3);
        atomicAdd(&g_hist[bucket_of(p0.x, p0.y, p0.z)], 1);
        atomicAdd(&g_hist[bucket_of(p1.x, p1.y, p1.z)], 1);
        atomicAdd(&g_hist[bucket_of(p2.x, p2.y, p2.z)], 1);
        atomicAdd(&g_hist[bucket_of(p3.x, p3.y, p3.z)], 1);
    } else {
        for (int i = i0; i < B; i++) {
            int k = bucket_of(xyz[i * 3 + 0], xyz[i * 3 + 1], xyz[i * 3 + 2]);
            atomicAdd(&g_hist[k], 1);
        }
    }
}

// ---------------- kernel 2: scan (PDL secondary) ----------------
// Base assignment order is nondeterministic but every point's OUTPUT depends
// only on its own xyz, so d_out is bit-identical for any g_sorted permutation.
__global__ void __launch_bounds__(1024) scan_fused_kernel() {
    cudaGridDependencySynchronize();

    __shared__ int wsum[32];
    __shared__ int sbase;
    int t = threadIdx.x, b = blockIdx.x;
    int lane = t & 31, w = t >> 5;
    int v = g_hist[b * 1024 + t];

    int s = v;
#pragma unroll
    for (int o = 1; o < 32; o <<= 1) {
        int x = __shfl_up_sync(0xFFFFFFFFu, s, o);
        if (lane >= o) s += x;
    }
    if (lane == 31) wsum[w] = s;
    __syncthreads();
    if (w == 0) {
        int ws = wsum[lane];
        int t2 = ws;
#pragma unroll
        for (int o = 1; o < 32; o <<= 1) {
            int x = __shfl_up_sync(0xFFFFFFFFu, t2, o);
            if (lane >= o) t2 += x;
        }
        wsum[lane] = t2 - ws;
    }
    __syncthreads();
    int incl = s + wsum[w];
    if (t == 1023) sbase = atomicAdd(&g_hist[NB], incl);
    __syncthreads();
    g_hist[b * 1024 + t] = (incl - v) + sbase;
}

// ---------------- kernel 3: scatter (4 pts/thread) + dense build (PDL) ------
__device__ __forceinline__ float2 dense_lookup(const float2* emb, int x, int y, int z,
                                               int size, int off) {
    unsigned long long h = (unsigned long long)(unsigned)x
        ^ ((unsigned long long)(unsigned)y * 2654435761ull)
        ^ ((unsigned long long)(unsigned)z * 805459861ull);
    int idx = (int)(h % (unsigned long long)size) + off;
    return emb[idx];
}

__device__ __forceinline__ void scat1(float3 p, int i) {
    int k = bucket_of(p.x, p.y, p.z);
    int pos = atomicAdd(&g_hist[k], 1);
    __stcs(&g_sorted[pos], make_float4(p.x, p.y, p.z, __int_as_float(i)));
}

__global__ void __launch_bounds__(256) scatter_build_kernel(
    const float* __restrict__ xyz,
    const float2* __restrict__ emb, int B)
{
    unsigned blk = blockIdx.x;
    unsigned nscat = (unsigned)((B + 1023) / 1024);
    if (blk < nscat) {
        int i0 = (blk * 256 + threadIdx.x) * 4;
        if (i0 + 3 < B) {
            float3 p0, p1, p2, p3;
            load4pts((const float4*)xyz, i0, p0, p1, p2, p3);
            cudaGridDependencySynchronize();
            scat1(p0, i0);
            scat1(p1, i0 + 1);
            scat1(p2, i0 + 2);
            scat1(p3, i0 + 3);
        } else {
            cudaGridDependencySynchronize();
            for (int i = i0; i < B; i++) {
                float3 p = make_float3(xyz[i * 3 + 0], xyz[i * 3 + 1], xyz[i * 3 + 2]);
                scat1(p, i);
            }
        }
    } else {
        int i = (blk - nscat) * 256 + threadIdx.x;
        if (i >= DTOTAL) return;
#pragma unroll
        for (int l = 0; l < 7; l++) {
            const int lo = OFF_(l);
            const int hi = lo + DSIZE_(l);
            if (i >= lo && i < hi) {
                const int R = RES_(l) + 1;
                int local = i - lo;
                int z = local % R;
                int t = local / R;
                int y = t % R;
                int x = t / R;
                float2 a = dense_lookup(emb, x, y, z, DSIZE_(l), OFF_(l));
                int z1 = (z + 1 < R) ? (z + 1) : z;
                float2 b = dense_lookup(emb, x, y, z1, DSIZE_(l), OFF_(l));
                g_densep[i] = make_float4(a.x, a.y, b.x, b.y);
            }
        }
    }
}

// ---------------- main kernel: role-split levels (PDL secondary) ------------
// Blocks [0, nblkP):        levels 0-7  -> out cols [0, 19)  (xyz + 8 levels)
// Blocks [nblkP, 2*nblkP):  levels 8-15 -> out cols [19, 35)
// Each role carries half the live register state -> fits 51 regs at
// __launch_bounds__(256,5) WITHOUT losing load batching (unlike R10, which
// forced all 16 levels into a smaller reg budget) -> 40 warps/SM.
__device__ __forceinline__ float2 lerp2(float2 a, float2 b, float t) {
    float2 r;
    r.x = __fmaf_rn(t, b.x - a.x, a.x);
    r.y = __fmaf_rn(t, b.y - a.y, a.y);
    return r;
}
__device__ __forceinline__ float2 lo2(float4 v) { return make_float2(v.x, v.y); }
__device__ __forceinline__ float2 hi2(float4 v) { return make_float2(v.z, v.w); }

// one hashed level (size 2^19), pow2 + x-pairing trick
__device__ __forceinline__ float2 hashed_level(const float* __restrict__ embf,
                                               int LOFF, int ix, int iy, int iz,
                                               float fx, float fy, float fz) {
    const unsigned MASK = 0x7FFFFu;
    unsigned hy0 = (unsigned)iy * 2654435761u;
    unsigned hy1 = hy0 + 2654435761u;
    unsigned hz0 = (unsigned)iz * 805459861u;
    unsigned hz1 = hz0 + 805459861u;
    unsigned x0 = (unsigned)ix;
    unsigned x1 = x0 + 1u;
    unsigned c00 = hy0 ^ hz0;
    unsigned c01 = hy0 ^ hz1;
    unsigned c10 = hy1 ^ hz0;
    unsigned c11 = hy1 ^ hz1;
    const bool xodd = (x0 & 1u) != 0u;

    const float4* __restrict__ p4 = (const float4*)(embf + 2 * LOFF);

    unsigned i0_00 = (x0 ^ c00) & MASK, i1_00 = (x1 ^ c00) & MASK;
    unsigned i0_01 = (x0 ^ c01) & MASK, i1_01 = (x1 ^ c01) & MASK;
    unsigned i0_10 = (x0 ^ c10) & MASK, i1_10 = (x1 ^ c10) & MASK;
    unsigned i0_11 = (x0 ^ c11) & MASK, i1_11 = (x1 ^ c11) & MASK;

    float4 a00 = p4[i0_00 >> 1];
    float4 a01 = p4[i0_01 >> 1];
    float4 a10 = p4[i0_10 >> 1];
    float4 a11 = p4[i0_11 >> 1];

    float4 b00, b01, b10, b11;
    if (xodd) {
        b00 = p4[i1_00 >> 1];
        b01 = p4[i1_01 >> 1];
        b10 = p4[i1_10 >> 1];
        b11 = p4[i1_11 >> 1];
    } else {
        b00 = a00; b01 = a01; b10 = a10; b11 = a11;
    }

    bool q00p = (i0_00 & 1u), q01p = (i0_01 & 1u),
         q10p = (i0_10 & 1u), q11p = (i0_11 & 1u);

    float2 e0_00 = q00p ? hi2(a00) : lo2(a00);
    float2 e0_01 = q01p ? hi2(a01) : lo2(a01);
    float2 e0_10 = q10p ? hi2(a10) : lo2(a10);
    float2 e0_11 = q11p ? hi2(a11) : lo2(a11);
    float2 e1_00 = q00p ? lo2(b00) : hi2(b00);
    float2 e1_01 = q01p ? lo2(b01) : hi2(b01);
    float2 e1_10 = q10p ? lo2(b10) : hi2(b10);
    float2 e1_11 = q11p ? lo2(b11) : hi2(b11);

    float2 t00 = lerp2(e0_00, e1_00, fx);
    float2 t01 = lerp2(e0_01, e1_01, fx);
    float2 t10 = lerp2(e0_10, e1_10, fx);
    float2 t11 = lerp2(e0_11, e1_11, fx);
    float2 u0 = lerp2(t00, t01, fz);
    float2 u1 = lerp2(t10, t11, fz);
    return lerp2(u0, u1, fy);
}

__global__ void __launch_bounds__(256, 5) hashgrid_split_kernel(
    const float* __restrict__ xyz,
    const float* __restrict__ embf,
    float* __restrict__ out,
    int B, int nblkP, int use_sorted)
{
    if (use_sorted) cudaGridDependencySynchronize();  // scatter+build complete

    __shared__ __align__(16) float s[256 * 19];   // role A: 19 floats; role B: 16
    __shared__ int srow[256];

    const int tid = threadIdx.x;
    const bool roleB = (int)blockIdx.x >= nblkP;
    const int pb = roleB ? ((int)blockIdx.x - nblkP) : (int)blockIdx.x;
    const long long j = (long long)pb * 256 + tid;

    // re-zero g_hist for the next graph replay (role A blocks only)
    if (!roleB) {
        for (long long zi = j; zi < NB + 1; zi += (long long)nblkP * 256)
            g_hist[zi] = 0;
    }

    const int NOUT = roleB ? 16 : 19;

    int orig = -1;
    if (j < B) {
        float px, py, pz;
        if (use_sorted) {
            float4 sd = __ldcs(&g_sorted[j]);   // read-once: evict-first
            px = sd.x; py = sd.y; pz = sd.z;
            orig = __float_as_int(sd.w);
        } else {
            px = xyz[j * 3 + 0];
            py = xyz[j * 3 + 1];
            pz = xyz[j * 3 + 2];
            orig = (int)j;
        }

        // norm = (v - MIN) / (MAX - MIN), IEEE ops to match reference exactly
        const float nx = __fdiv_rn(__fadd_rn(px, 0.75f), 1.5f);
        const float ny = __fdiv_rn(__fadd_rn(py, 0.75f), 1.5f);
        const float nz = __fdiv_rn(__fadd_rn(pz, 0.75f), 1.5f);

        float* sp = &s[tid * NOUT];

        if (!roleB) {
            // ---- role A: xyz + levels 0..7 ----
            sp[0] = px; sp[1] = py; sp[2] = pz;
#pragma unroll
            for (int l = 0; l < 8; l++) {
                const float rf = (float)RES_(l);
                float posx = __fmul_rn(nx, rf);
                float posy = __fmul_rn(ny, rf);
                float posz = __fmul_rn(nz, rf);
                float bfx = floorf(posx);
                float bfy = floorf(posy);
                float bfz = floorf(posz);
                float fx = __fadd_rn(posx, -bfx);
                float fy = __fadd_rn(posy, -bfy);
                float fz = __fadd_rn(posz, -bfz);
                int ix = (int)bfx;
                int iy = (int)bfy;
                int iz = (int)bfz;

                float2 v;
                if (l < 7) {
                    const int R = RES_(l) + 1;
                    const float4* __restrict__ p =
                        g_densep + (OFF_(l) + (ix * R + iy) * R + iz);
                    float4 q00 = p[0];
                    float4 q01 = p[R];
                    float4 q10 = p[R * R];
                    float4 q11 = p[R * R + R];

                    float2 t00 = lerp2(lo2(q00), hi2(q00), fz);
                    float2 t01 = lerp2(lo2(q01), hi2(q01), fz);
                    float2 t10 = lerp2(lo2(q10), hi2(q10), fz);
                    float2 t11 = lerp2(lo2(q11), hi2(q11), fz);
                    float2 u0 = lerp2(t00, t01, fy);
                    float2 u1 = lerp2(t10, t11, fy);
                    v = lerp2(u0, u1, fx);
                } else {
                    v = hashed_level(embf, OFF_(7), ix, iy, iz, fx, fy, fz);
                }
                sp[3 + 2 * l]     = v.x;
                sp[3 + 2 * l + 1] = v.y;
            }
        } else {
            // ---- role B: levels 8..15 (all hashed, size 2^19) ----
#pragma unroll
            for (int l = 8; l < 16; l++) {
                const float rf = (float)RES_(l);
                float posx = __fmul_rn(nx, rf);
                float posy = __fmul_rn(ny, rf);
                float posz = __fmul_rn(nz, rf);
                float bfx = floorf(posx);
                float bfy = floorf(posy);
                float bfz = floorf(posz);
                float fx = __fadd_rn(posx, -bfx);
                float fy = __fadd_rn(posy, -bfy);
                float fz = __fadd_rn(posz, -bfz);
                int ix = (int)bfx;
                int iy = (int)bfy;
                int iz = (int)bfz;

                float2 v = hashed_level(embf, OFF_(l), ix, iy, iz, fx, fy, fz);
                sp[2 * (l - 8)]     = v.x;
                sp[2 * (l - 8) + 1] = v.y;
            }
        }
    }
    srow[tid] = orig;

    __syncthreads();

    // warp-cooperative partial-row writes, streaming
    const int warp = tid >> 5;
    const int lane = tid & 31;
    const int colbase = roleB ? 19 : 0;
#pragma unroll 4
    for (int r = 0; r < 32; r++) {
        int p = warp * 32 + r;
        int row = srow[p];
        if (row >= 0 && lane < NOUT) {
            const float* src = &s[p * NOUT];
            long long base = (long long)row * 35 + colbase;
            __stcs(&out[base + lane], src[lane]);
        }
    }
}

// ---------------- launch ----------------
static void launch_pdl(void* func, dim3 grid, dim3 block, void** args)
{
    cudaLaunchConfig_t cfg = {};
    cfg.gridDim = grid;
    cfg.blockDim = block;
    cfg.dynamicSmemBytes = 0;
    cfg.stream = 0;
    cudaLaunchAttribute attr[1];
    attr[0].id = cudaLaunchAttributeProgrammaticStreamSerialization;
    attr[0].val.programmaticStreamSerializationAllowed = 1;
    cfg.attrs = attr;
    cfg.numAttrs = 1;
    cudaLaunchKernelExC(&cfg, func, args);
}

extern "C" void kernel_launch(void* const* d_in, const int* in_sizes, int n_in,
                              void* d_out, int out_size)
{
    const float* xyz = (const float*)d_in[0];
    const float* emb = (const float*)d_in[1];
    float* out = (float*)d_out;
    const int B = in_sizes[0] / 3;
    int nblkP = (B + 255) / 256;           // per-role block count
    const int nblk4 = (B + 1023) / 1024;   // keyhist/scatter (4 pts/thread)

    if (B > 0 && B <= MAXB) {
        keyhist_kernel<<<nblk4, 256>>>(xyz, B);

        launch_pdl((void*)scan_fused_kernel, dim3(NB / 1024), dim3(1024), nullptr);

        const float2* emb2 = (const float2*)emb;
        void* sargs[3] = { (void*)&xyz, (void*)&emb2, (void*)&B };
        launch_pdl((void*)scatter_build_kernel, dim3(nblk4 + NBLK_A), dim3(256), sargs);

        int one = 1;
        void* hargs[6] = { (void*)&xyz, (void*)&emb, (void*)&out,
                           (void*)&B, (void*)&nblkP, (void*)&one };
        launch_pdl((void*)hashgrid_split_kernel, dim3(2 * nblkP), dim3(256), hargs);
    } else if (B > 0) {
        scatter_build_kernel<<<NBLK_A, 256>>>(xyz, (const float2*)emb, 0);
        int zero = 0;
        hashgrid_split_kernel<<<2 * nblkP, 256>>>(xyz, emb, out, B, nblkP, zero);
    }
}

// round 16
// speedup vs baseline: 1.7787x; 1.7787x over previous
#include <cuda_runtime.h>
#include <stdint.h>

// ---------------- level geometry (verified: sum of sizes == 5262476) ----------------
#define NLVL 16

static __device__ __forceinline__ constexpr int RES_(int l) {
    constexpr int r[16] = {16,20,25,32,40,50,64,80,101,128,161,203,256,322,406,512};
    return r[l];
}
static __device__ __forceinline__ constexpr int OFF_(int l) {
    constexpr int o[16] = {0,4913,14174,31750,67687,136608,269259,543884,
                           1068172,1592460,2116748,2641036,3165324,3689612,4213900,4738188};
    return o[l];
}
static __device__ __forceinline__ constexpr int DSIZE_(int l) {
    constexpr int s[7] = {4913,9261,17576,35937,68921,132651,274625};
    return s[l];
}
#define DTOTAL 543884
#define NBLK_A ((DTOTAL + 255) / 256)

// De-hashed dense z-pair tables for levels 0..6 ONLY (L7/L8 spatial tables
// tried in R8/R9: extra L2 footprint cancelled their savings — reverted).
// g_densep[off + (x*R+y)*R + z] = { emb[h(x,y,z)], emb[h(x,y,z+1)] }
__device__ float4 g_densep[DTOTAL];

// ---------------- sort scratch ----------------
#define NB   262144             // 64^3 morton buckets
#define MAXB (1 << 20)
__device__ int    g_hist[NB + 1];   // [NB] = global base counter; zero-init at load,
                                    // re-zeroed by hashgrid_kernel each run
__device__ float4 g_sorted[MAXB];   // {x, y, z, bitcast(orig_idx)}

// ---------------- morton bucketing (6 bits/dim -> 64^3 buckets) ----------------
__device__ __forceinline__ unsigned spread3(unsigned v) {
    v &= 0x3Fu;
    v = (v | (v << 8)) & 0x0300F00Fu;
    v = (v | (v << 4)) & 0x030C30C3u;
    v = (v | (v << 2)) & 0x09249249u;
    return v;
}
__device__ __forceinline__ int bucket_of(float px, float py, float pz) {
    float nx = (px + 0.75f) * (1.0f / 1.5f);
    float ny = (py + 0.75f) * (1.0f / 1.5f);
    float nz = (pz + 0.75f) * (1.0f / 1.5f);
    int cx = (int)(nx * 64.0f); cx = cx < 0 ? 0 : (cx > 63 ? 63 : cx);
    int cy = (int)(ny * 64.0f); cy = cy < 0 ? 0 : (cy > 63 ? 63 : cy);
    int cz = (int)(nz * 64.0f); cz = cz < 0 ? 0 : (cz > 63 ? 63 : cz);
    return (int)(spread3((unsigned)cx) | (spread3((unsigned)cy) << 1)
               | (spread3((unsigned)cz) << 2));
}

// decode 4 points from 3 float4 vector loads (base point index i0, i0 % 4 == 0)
__device__ __forceinline__ void load4pts(const float4* __restrict__ x4, int i0,
                                         float3& p0, float3& p1, float3& p2, float3& p3) {
    int f = (i0 * 3) >> 2;          // i0 multiple of 4 -> exact
    float4 v0 = x4[f], v1 = x4[f + 1], v2 = x4[f + 2];
    p0 = make_float3(v0.x, v0.y, v0.z);
    p1 = make_float3(v0.w, v1.x, v1.y);
    p2 = make_float3(v1.z, v1.w, v2.x);
    p3 = make_float3(v2.y, v2.z, v2.w);
}

// ---------------- kernel 1: key histogram (4 points/thread) ----------------
__global__ void __launch_bounds__(256) keyhist_kernel(const float* __restrict__ xyz, int B) {
    int i0 = (blockIdx.x * 256 + threadIdx.x) * 4;
    if (i0 + 3 < B) {
        float3 p0, p1, p2, p3;
        load4pts((const float4*)xyz, i0, p0, p1, p2, p3);
        atomicAdd(&g_hist[bucket_of(p0.x, p0.y, p0.z)], 1);
        atomicAdd(&g_hist[bucket_of(p1.x, p1.y, p1.z)], 1);
        atomicAdd(&g_hist[bucket_of(p2.x, p2.y, p2.z)], 1);
        atomicAdd(&g_hist[bucket_of(p3.x, p3.y, p3.z)], 1);
    } else {
        for (int i = i0; i < B; i++) {
            int k = bucket_of(xyz[i * 3 + 0], xyz[i * 3 + 1], xyz[i * 3 + 2]);
            atomicAdd(&g_hist[k], 1);
        }
    }
}

// ---------------- kernel 2: scan (PDL secondary) ----------------
// Base assignment order is nondeterministic but every point's OUTPUT depends
// only on its own xyz, so d_out is bit-identical for any g_sorted permutation.
__global__ void __launch_bounds__(1024) scan_fused_kernel() {
    cudaGridDependencySynchronize();   // wait for keyhist's atomics to land

    __shared__ int wsum[32];
    __shared__ int sbase;
    int t = threadIdx.x, b = blockIdx.x;
    int lane = t & 31, w = t >> 5;
    int v = g_hist[b * 1024 + t];

    int s = v;
#pragma unroll
    for (int o = 1; o < 32; o <<= 1) {
        int x = __shfl_up_sync(0xFFFFFFFFu, s, o);
        if (lane >= o) s += x;
    }
    if (lane == 31) wsum[w] = s;
    __syncthreads();
    if (w == 0) {
        int ws = wsum[lane];
        int t2 = ws;
#pragma unroll
        for (int o = 1; o < 32; o <<= 1) {
            int x = __shfl_up_sync(0xFFFFFFFFu, t2, o);
            if (lane >= o) t2 += x;
        }
        wsum[lane] = t2 - ws;
    }
    __syncthreads();
    int incl = s + wsum[w];
    if (t == 1023) sbase = atomicAdd(&g_hist[NB], incl);
    __syncthreads();
    g_hist[b * 1024 + t] = (incl - v) + sbase;
}

// ---------------- kernel 3: scatter (4 pts/thread) + dense build (PDL) ------
__device__ __forceinline__ float2 dense_lookup(const float2* emb, int x, int y, int z,
                                               int size, int off) {
    unsigned long long h = (unsigned long long)(unsigned)x
        ^ ((unsigned long long)(unsigned)y * 2654435761ull)
        ^ ((unsigned long long)(unsigned)z * 805459861ull);
    int idx = (int)(h % (unsigned long long)size) + off;
    return emb[idx];
}

__device__ __forceinline__ void scat1(float3 p, int i) {
    int k = bucket_of(p.x, p.y, p.z);
    int pos = atomicAdd(&g_hist[k], 1);
    __stcs(&g_sorted[pos], make_float4(p.x, p.y, p.z, __int_as_float(i)));
}

__global__ void __launch_bounds__(256) scatter_build_kernel(
    const float* __restrict__ xyz,
    const float2* __restrict__ emb, int B)
{
    unsigned blk = blockIdx.x;
    unsigned nscat = (unsigned)((B + 1023) / 1024);
    if (blk < nscat) {
        int i0 = (blk * 256 + threadIdx.x) * 4;
        // independent prologue: loads + hashes run while scan executes
        if (i0 + 3 < B) {
            float3 p0, p1, p2, p3;
            load4pts((const float4*)xyz, i0, p0, p1, p2, p3);
            cudaGridDependencySynchronize();   // scan's bases now visible
            scat1(p0, i0);
            scat1(p1, i0 + 1);
            scat1(p2, i0 + 2);
            scat1(p3, i0 + 3);
        } else {
            cudaGridDependencySynchronize();
            for (int i = i0; i < B; i++) {
                float3 p = make_float3(xyz[i * 3 + 0], xyz[i * 3 + 1], xyz[i * 3 + 2]);
                scat1(p, i);
            }
        }
    } else {
        // dense-table build: independent of keyhist/scan — no sync needed
        int i = (blk - nscat) * 256 + threadIdx.x;
        if (i >= DTOTAL) return;
#pragma unroll
        for (int l = 0; l < 7; l++) {
            const int lo = OFF_(l);
            const int hi = lo + DSIZE_(l);
            if (i >= lo && i < hi) {
                const int R = RES_(l) + 1;
                int local = i - lo;
                int z = local % R;
                int t = local / R;
                int y = t % R;
                int x = t / R;
                float2 a = dense_lookup(emb, x, y, z, DSIZE_(l), OFF_(l));
                int z1 = (z + 1 < R) ? (z + 1) : z;  // z=R-1 never read as a base
                float2 b = dense_lookup(emb, x, y, z1, DSIZE_(l), OFF_(l));
                g_densep[i] = make_float4(a.x, a.y, b.x, b.y);
            }
        }
    }
}

// ---------------- main kernel (PDL secondary — sync at top) ----------------
__device__ __forceinline__ float2 lerp2(float2 a, float2 b, float t) {
    float2 r;
    r.x = __fmaf_rn(t, b.x - a.x, a.x);
    r.y = __fmaf_rn(t, b.y - a.y, a.y);
    return r;
}
__device__ __forceinline__ float2 lo2(float4 v) { return make_float2(v.x, v.y); }
__device__ __forceinline__ float2 hi2(float4 v) { return make_float2(v.z, v.w); }

__global__ void __launch_bounds__(256, 4) hashgrid_kernel(
    const float* __restrict__ xyz,
    const float* __restrict__ embf,
    float* __restrict__ out,
    int B, int use_sorted)
{
    if (use_sorted) cudaGridDependencySynchronize();  // scatter+build complete

    __shared__ __align__(16) float s[256 * 35];
    __shared__ int srow[256];

    const int tid = threadIdx.x;
    const long long j = (long long)blockIdx.x * 256 + tid;

    // re-zero g_hist for the next graph replay (__device__ globals start zeroed)
    for (long long zi = j; zi < NB + 1; zi += (long long)gridDim.x * 256)
        g_hist[zi] = 0;

    int orig = -1;
    if (j < B) {
        float px, py, pz;
        if (use_sorted) {
            float4 sd = __ldcs(&g_sorted[j]);   // read-once: evict-first
            px = sd.x; py = sd.y; pz = sd.z;
            orig = __float_as_int(sd.w);
        } else {
            px = xyz[j * 3 + 0];
            py = xyz[j * 3 + 1];
            pz = xyz[j * 3 + 2];
            orig = (int)j;
        }

        // norm = (v - MIN) / (MAX - MIN), IEEE ops to match reference exactly
        const float nx = __fdiv_rn(__fadd_rn(px, 0.75f), 1.5f);
        const float ny = __fdiv_rn(__fadd_rn(py, 0.75f), 1.5f);
        const float nz = __fdiv_rn(__fadd_rn(pz, 0.75f), 1.5f);

        float* sp = &s[tid * 35];
        sp[0] = px; sp[1] = py; sp[2] = pz;

#pragma unroll
        for (int l = 0; l < NLVL; l++) {
            const float rf = (float)RES_(l);

            float posx = __fmul_rn(nx, rf);
            float posy = __fmul_rn(ny, rf);
            float posz = __fmul_rn(nz, rf);
            float bfx = floorf(posx);
            float bfy = floorf(posy);
            float bfz = floorf(posz);
            float fx = __fadd_rn(posx, -bfx);
            float fy = __fadd_rn(posy, -bfy);
            float fz = __fadd_rn(posz, -bfz);
            int ix = (int)bfx;
            int iy = (int)bfy;
            int iz = (int)bfz;

            float2 v;

            if (l < 7) {
                const int R = RES_(l) + 1;
                const float4* __restrict__ p =
                    g_densep + (OFF_(l) + (ix * R + iy) * R + iz);
                float4 q00 = p[0];
                float4 q01 = p[R];
                float4 q10 = p[R * R];
                float4 q11 = p[R * R + R];

                float2 t00 = lerp2(lo2(q00), hi2(q00), fz);
                float2 t01 = lerp2(lo2(q01), hi2(q01), fz);
                float2 t10 = lerp2(lo2(q10), hi2(q10), fz);
                float2 t11 = lerp2(lo2(q11), hi2(q11), fz);
                float2 u0 = lerp2(t00, t01, fy);
                float2 u1 = lerp2(t10, t11, fy);
                v = lerp2(u0, u1, fx);
            } else {
                const unsigned MASK = 0x7FFFFu;
                unsigned hy0 = (unsigned)iy * 2654435761u;
                unsigned hy1 = hy0 + 2654435761u;
                unsigned hz0 = (unsigned)iz * 805459861u;
                unsigned hz1 = hz0 + 805459861u;
                unsigned x0 = (unsigned)ix;
                unsigned x1 = x0 + 1u;
                unsigned c00 = hy0 ^ hz0;
                unsigned c01 = hy0 ^ hz1;
                unsigned c10 = hy1 ^ hz0;
                unsigned c11 = hy1 ^ hz1;
                const bool xodd = (x0 & 1u) != 0u;

                const float4* __restrict__ p4 = (const float4*)(embf + 2 * OFF_(l));

                unsigned i0_00 = (x0 ^ c00) & MASK, i1_00 = (x1 ^ c00) & MASK;
                unsigned i0_01 = (x0 ^ c01) & MASK, i1_01 = (x1 ^ c01) & MASK;
                unsigned i0_10 = (x0 ^ c10) & MASK, i1_10 = (x1 ^ c10) & MASK;
                unsigned i0_11 = (x0 ^ c11) & MASK, i1_11 = (x1 ^ c11) & MASK;

                float4 a00 = p4[i0_00 >> 1];
                float4 a01 = p4[i0_01 >> 1];
                float4 a10 = p4[i0_10 >> 1];
                float4 a11 = p4[i0_11 >> 1];

                float4 b00, b01, b10, b11;
                if (xodd) {
                    b00 = p4[i1_00 >> 1];
                    b01 = p4[i1_01 >> 1];
                    b10 = p4[i1_10 >> 1];
                    b11 = p4[i1_11 >> 1];
                } else {
                    b00 = a00; b01 = a01; b10 = a10; b11 = a11;
                }

                bool q00p = (i0_00 & 1u), q01p = (i0_01 & 1u),
                     q10p = (i0_10 & 1u), q11p = (i0_11 & 1u);

                float2 e0_00 = q00p ? hi2(a00) : lo2(a00);
                float2 e0_01 = q01p ? hi2(a01) : lo2(a01);
                float2 e0_10 = q10p ? hi2(a10) : lo2(a10);
                float2 e0_11 = q11p ? hi2(a11) : lo2(a11);
                float2 e1_00 = q00p ? lo2(b00) : hi2(b00);
                float2 e1_01 = q01p ? lo2(b01) : hi2(b01);
                float2 e1_10 = q10p ? lo2(b10) : hi2(b10);
                float2 e1_11 = q11p ? lo2(b11) : hi2(b11);

                float2 t00 = lerp2(e0_00, e1_00, fx);
                float2 t01 = lerp2(e0_01, e1_01, fx);
                float2 t10 = lerp2(e0_10, e1_10, fx);
                float2 t11 = lerp2(e0_11, e1_11, fx);
                float2 u0 = lerp2(t00, t01, fz);
                float2 u1 = lerp2(t10, t11, fz);
                v = lerp2(u0, u1, fy);
            }

            sp[3 + 2 * l]     = v.x;
            sp[3 + 2 * l + 1] = v.y;
        }
    }
    srow[tid] = orig;

    __syncthreads();

    // warp-cooperative row writes, streaming (output is write-once)
    const int warp = tid >> 5;
    const int lane = tid & 31;
#pragma unroll 4
    for (int r = 0; r < 32; r++) {
        int p = warp * 32 + r;
        int row = srow[p];
        if (row >= 0) {
            const float* src = &s[p * 35];
            long long base = (long long)row * 35;
            __stcs(&out[base + lane], src[lane]);
            if (lane < 3) __stcs(&out[base + 32 + lane], src[32 + lane]);
        }
    }
}

// ---------------- launch ----------------
static void launch_pdl(void* func, dim3 grid, dim3 block, void** args)
{
    cudaLaunchConfig_t cfg = {};
    cfg.gridDim = grid;
    cfg.blockDim = block;
    cfg.dynamicSmemBytes = 0;
    cfg.stream = 0;   // legacy stream (the one the harness captures)
    cudaLaunchAttribute attr[1];
    attr[0].id = cudaLaunchAttributeProgrammaticStreamSerialization;
    attr[0].val.programmaticStreamSerializationAllowed = 1;
    cfg.attrs = attr;
    cfg.numAttrs = 1;
    cudaLaunchKernelExC(&cfg, func, args);
}

extern "C" void kernel_launch(void* const* d_in, const int* in_sizes, int n_in,
                              void* d_out, int out_size)
{
    const float* xyz = (const float*)d_in[0];
    const float* emb = (const float*)d_in[1];
    float* out = (float*)d_out;
    const int B = in_sizes[0] / 3;
    const int nblk = (B + 255) / 256;      // hashgrid grid (1 pt/thread)
    const int nblk4 = (B + 1023) / 1024;   // keyhist/scatter grids (4 pts/thread)

    if (B > 0 && B <= MAXB) {
        keyhist_kernel<<<nblk4, 256>>>(xyz, B);

        launch_pdl((void*)scan_fused_kernel, dim3(NB / 1024), dim3(1024), nullptr);

        const float2* emb2 = (const float2*)emb;
        void* sargs[3] = { (void*)&xyz, (void*)&emb2, (void*)&B };
        launch_pdl((void*)scatter_build_kernel, dim3(nblk4 + NBLK_A), dim3(256), sargs);

        int one = 1;
        void* hargs[5] = { (void*)&xyz, (void*)&emb, (void*)&out, (void*)&B, (void*)&one };
        launch_pdl((void*)hashgrid_kernel, dim3(nblk), dim3(256), hargs);
    } else if (B > 0) {
        scatter_build_kernel<<<NBLK_A, 256>>>(xyz, (const float2*)emb, 0);
        hashgrid_kernel<<<nblk, 256>>>(xyz, emb, out, B, 0);
    }
}

// round 17
// speedup vs baseline: 1.7857x; 1.0039x over previous
#include <cuda_runtime.h>
#include <stdint.h>

// ---------------- level geometry (verified: sum of sizes == 5262476) ----------------
#define NLVL 16

static __device__ __forceinline__ constexpr int RES_(int l) {
    constexpr int r[16] = {16,20,25,32,40,50,64,80,101,128,161,203,256,322,406,512};
    return r[l];
}
static __device__ __forceinline__ constexpr int OFF_(int l) {
    constexpr int o[16] = {0,4913,14174,31750,67687,136608,269259,543884,
                           1068172,1592460,2116748,2641036,3165324,3689612,4213900,4738188};
    return o[l];
}
static __device__ __forceinline__ constexpr int DSIZE_(int l) {
    constexpr int s[7] = {4913,9261,17576,35937,68921,132651,274625};
    return s[l];
}
#define DTOTAL 543884
#define NBLK_A ((DTOTAL + 255) / 256)

// De-hashed dense z-pair tables for levels 0..6 ONLY (L7/L8 spatial tables
// tried in R8/R9: extra L2 footprint cancelled their savings — reverted).
// g_densep[off + (x*R+y)*R + z] = { emb[h(x,y,z)], emb[h(x,y,z+1)] }
__device__ float4 g_densep[DTOTAL];

// ---------------- sort scratch ----------------
#define NB   262144             // 64^3 morton buckets
#define MAXB (1 << 20)
__device__ int    g_hist[NB + 1];   // [NB] = global base counter; zero-init at load,
                                    // re-zeroed by hashgrid_kernel each run
__device__ float4 g_sorted[MAXB];   // {x, y, z, bitcast(orig_idx)}

// ---------------- morton bucketing (6 bits/dim -> 64^3 buckets) ----------------
__device__ __forceinline__ unsigned spread3(unsigned v) {
    v &= 0x3Fu;
    v = (v | (v << 8)) & 0x0300F00Fu;
    v = (v | (v << 4)) & 0x030C30C3u;
    v = (v | (v << 2)) & 0x09249249u;
    return v;
}
__device__ __forceinline__ int bucket_of(float px, float py, float pz) {
    float nx = (px + 0.75f) * (1.0f / 1.5f);
    float ny = (py + 0.75f) * (1.0f / 1.5f);
    float nz = (pz + 0.75f) * (1.0f / 1.5f);
    int cx = (int)(nx * 64.0f); cx = cx < 0 ? 0 : (cx > 63 ? 63 : cx);
    int cy = (int)(ny * 64.0f); cy = cy < 0 ? 0 : (cy > 63 ? 63 : cy);
    int cz = (int)(nz * 64.0f); cz = cz < 0 ? 0 : (cz > 63 ? 63 : cz);
    return (int)(spread3((unsigned)cx) | (spread3((unsigned)cy) << 1)
               | (spread3((unsigned)cz) << 2));
}

// decode 4 points from 3 float4 vector loads (base point index i0, i0 % 4 == 0)
__device__ __forceinline__ void load4pts(const float4* __restrict__ x4, int i0,
                                         float3& p0, float3& p1, float3& p2, float3& p3) {
    int f = (i0 * 3) >> 2;          // i0 multiple of 4 -> exact
    float4 v0 = x4[f], v1 = x4[f + 1], v2 = x4[f + 2];
    p0 = make_float3(v0.x, v0.y, v0.z);
    p1 = make_float3(v0.w, v1.x, v1.y);
    p2 = make_float3(v1.z, v1.w, v2.x);
    p3 = make_float3(v2.y, v2.z, v2.w);
}

// ---------------- kernel 1: key histogram (4 points/thread) ----------------
__global__ void __launch_bounds__(256) keyhist_kernel(const float* __restrict__ xyz, int B) {
    int i0 = (blockIdx.x * 256 + threadIdx.x) * 4;
    if (i0 + 3 < B) {
        float3 p0, p1, p2, p3;
        load4pts((const float4*)xyz, i0, p0, p1, p2, p3);
        atomicAdd(&g_hist[bucket_of(p0.x, p0.y, p0.z)], 1);
        atomicAdd(&g_hist[bucket_of(p1.x, p1.y, p1.z)], 1);
        atomicAdd(&g_hist[bucket_of(p2.x, p2.y, p2.z)], 1);
        atomicAdd(&g_hist[bucket_of(p3.x, p3.y, p3.z)], 1);
    } else {
        for (int i = i0; i < B; i++) {
            int k = bucket_of(xyz[i * 3 + 0], xyz[i * 3 + 1], xyz[i * 3 + 2]);
            atomicAdd(&g_hist[k], 1);
        }
    }
}

// ---------------- kernel 2: scan (PDL secondary) ----------------
// Base assignment order is nondeterministic but every point's OUTPUT depends
// only on its own xyz, so d_out is bit-identical for any g_sorted permutation.
__global__ void __launch_bounds__(1024) scan_fused_kernel() {
    cudaGridDependencySynchronize();   // wait for keyhist's atomics to land

    __shared__ int wsum[32];
    __shared__ int sbase;
    int t = threadIdx.x, b = blockIdx.x;
    int lane = t & 31, w = t >> 5;
    int v = g_hist[b * 1024 + t];

    int s = v;
#pragma unroll
    for (int o = 1; o < 32; o <<= 1) {
        int x = __shfl_up_sync(0xFFFFFFFFu, s, o);
        if (lane >= o) s += x;
    }
    if (lane == 31) wsum[w] = s;
    __syncthreads();
    if (w == 0) {
        int ws = wsum[lane];
        int t2 = ws;
#pragma unroll
        for (int o = 1; o < 32; o <<= 1) {
            int x = __shfl_up_sync(0xFFFFFFFFu, t2, o);
            if (lane >= o) t2 += x;
        }
        wsum[lane] = t2 - ws;
    }
    __syncthreads();
    int incl = s + wsum[w];
    if (t == 1023) sbase = atomicAdd(&g_hist[NB], incl);
    __syncthreads();
    g_hist[b * 1024 + t] = (incl - v) + sbase;
}

// ---------------- kernel 3: scatter (4 pts/thread) + dense build (PDL) ------
__device__ __forceinline__ float2 dense_lookup(const float2* emb, int x, int y, int z,
                                               int size, int off) {
    unsigned long long h = (unsigned long long)(unsigned)x
        ^ ((unsigned long long)(unsigned)y * 2654435761ull)
        ^ ((unsigned long long)(unsigned)z * 805459861ull);
    int idx = (int)(h % (unsigned long long)size) + off;
    return emb[idx];
}

__device__ __forceinline__ void scat1(float3 p, int i) {
    int k = bucket_of(p.x, p.y, p.z);
    int pos = atomicAdd(&g_hist[k], 1);
    __stcs(&g_sorted[pos], make_float4(p.x, p.y, p.z, __int_as_float(i)));
}

__global__ void __launch_bounds__(256) scatter_build_kernel(
    const float* __restrict__ xyz,
    const float2* __restrict__ emb, int B)
{
    unsigned blk = blockIdx.x;
    unsigned nscat = (unsigned)((B + 1023) / 1024);
    if (blk < nscat) {
        int i0 = (blk * 256 + threadIdx.x) * 4;
        // independent prologue: loads + hashes run while scan executes
        if (i0 + 3 < B) {
            float3 p0, p1, p2, p3;
            load4pts((const float4*)xyz, i0, p0, p1, p2, p3);
            cudaGridDependencySynchronize();   // scan's bases now visible
            scat1(p0, i0);
            scat1(p1, i0 + 1);
            scat1(p2, i0 + 2);
            scat1(p3, i0 + 3);
        } else {
            cudaGridDependencySynchronize();
            for (int i = i0; i < B; i++) {
                float3 p = make_float3(xyz[i * 3 + 0], xyz[i * 3 + 1], xyz[i * 3 + 2]);
                scat1(p, i);
            }
        }
    } else {
        // dense-table build: independent of keyhist/scan — no sync needed
        int i = (blk - nscat) * 256 + threadIdx.x;
        if (i >= DTOTAL) return;
#pragma unroll
        for (int l = 0; l < 7; l++) {
            const int lo = OFF_(l);
            const int hi = lo + DSIZE_(l);
            if (i >= lo && i < hi) {
                const int R = RES_(l) + 1;
                int local = i - lo;
                int z = local % R;
                int t = local / R;
                int y = t % R;
                int x = t / R;
                float2 a = dense_lookup(emb, x, y, z, DSIZE_(l), OFF_(l));
                int z1 = (z + 1 < R) ? (z + 1) : z;  // z=R-1 never read as a base
                float2 b = dense_lookup(emb, x, y, z1, DSIZE_(l), OFF_(l));
                g_densep[i] = make_float4(a.x, a.y, b.x, b.y);
            }
        }
    }
}

// ---------------- main kernel (PDL secondary — sync at top) ----------------
__device__ __forceinline__ float2 lerp2(float2 a, float2 b, float t) {
    float2 r;
    r.x = __fmaf_rn(t, b.x - a.x, a.x);
    r.y = __fmaf_rn(t, b.y - a.y, a.y);
    return r;
}
__device__ __forceinline__ float2 lo2(float4 v) { return make_float2(v.x, v.y); }
__device__ __forceinline__ float2 hi2(float4 v) { return make_float2(v.z, v.w); }

__global__ void __launch_bounds__(256, 4) hashgrid_kernel(
    const float* __restrict__ xyz,
    const float* __restrict__ embf,
    float* __restrict__ out,
    int B, int use_sorted)
{
    if (use_sorted) cudaGridDependencySynchronize();  // scatter+build complete

    __shared__ __align__(16) float s[256 * 35];
    __shared__ int srow[256];

    const int tid = threadIdx.x;
    const long long j = (long long)blockIdx.x * 256 + tid;

    int orig = -1;
    if (j < B) {
        float px, py, pz;
        if (use_sorted) {
            float4 sd = __ldcs(&g_sorted[j]);   // read-once: evict-first
            px = sd.x; py = sd.y; pz = sd.z;
            orig = __float_as_int(sd.w);
        } else {
            px = xyz[j * 3 + 0];
            py = xyz[j * 3 + 1];
            pz = xyz[j * 3 + 2];
            orig = (int)j;
        }

        // norm = (v - MIN) / (MAX - MIN), IEEE ops to match reference exactly
        const float nx = __fdiv_rn(__fadd_rn(px, 0.75f), 1.5f);
        const float ny = __fdiv_rn(__fadd_rn(py, 0.75f), 1.5f);
        const float nz = __fdiv_rn(__fadd_rn(pz, 0.75f), 1.5f);

        float* sp = &s[tid * 35];
        sp[0] = px; sp[1] = py; sp[2] = pz;

#pragma unroll
        for (int l = 0; l < NLVL; l++) {
            const float rf = (float)RES_(l);

            float posx = __fmul_rn(nx, rf);
            float posy = __fmul_rn(ny, rf);
            float posz = __fmul_rn(nz, rf);
            float bfx = floorf(posx);
            float bfy = floorf(posy);
            float bfz = floorf(posz);
            float fx = __fadd_rn(posx, -bfx);
            float fy = __fadd_rn(posy, -bfy);
            float fz = __fadd_rn(posz, -bfz);
            int ix = (int)bfx;
            int iy = (int)bfy;
            int iz = (int)bfz;

            float2 v;

            if (l < 7) {
                const int R = RES_(l) + 1;
                const float4* __restrict__ p =
                    g_densep + (OFF_(l) + (ix * R + iy) * R + iz);
                float4 q00 = p[0];
                float4 q01 = p[R];
                float4 q10 = p[R * R];
                float4 q11 = p[R * R + R];

                float2 t00 = lerp2(lo2(q00), hi2(q00), fz);
                float2 t01 = lerp2(lo2(q01), hi2(q01), fz);
                float2 t10 = lerp2(lo2(q10), hi2(q10), fz);
                float2 t11 = lerp2(lo2(q11), hi2(q11), fz);
                float2 u0 = lerp2(t00, t01, fy);
                float2 u1 = lerp2(t10, t11, fy);
                v = lerp2(u0, u1, fx);
            } else {
                const unsigned MASK = 0x7FFFFu;
                unsigned hy0 = (unsigned)iy * 2654435761u;
                unsigned hy1 = hy0 + 2654435761u;
                unsigned hz0 = (unsigned)iz * 805459861u;
                unsigned hz1 = hz0 + 805459861u;
                unsigned x0 = (unsigned)ix;
                unsigned x1 = x0 + 1u;
                unsigned c00 = hy0 ^ hz0;
                unsigned c01 = hy0 ^ hz1;
                unsigned c10 = hy1 ^ hz0;
                unsigned c11 = hy1 ^ hz1;
                const bool xodd = (x0 & 1u) != 0u;

                const float4* __restrict__ p4 = (const float4*)(embf + 2 * OFF_(l));

                unsigned i0_00 = (x0 ^ c00) & MASK, i1_00 = (x1 ^ c00) & MASK;
                unsigned i0_01 = (x0 ^ c01) & MASK, i1_01 = (x1 ^ c01) & MASK;
                unsigned i0_10 = (x0 ^ c10) & MASK, i1_10 = (x1 ^ c10) & MASK;
                unsigned i0_11 = (x0 ^ c11) & MASK, i1_11 = (x1 ^ c11) & MASK;

                float4 a00 = p4[i0_00 >> 1];
                float4 a01 = p4[i0_01 >> 1];
                float4 a10 = p4[i0_10 >> 1];
                float4 a11 = p4[i0_11 >> 1];

                float4 b00, b01, b10, b11;
                if (xodd) {
                    b00 = p4[i1_00 >> 1];
                    b01 = p4[i1_01 >> 1];
                    b10 = p4[i1_10 >> 1];
                    b11 = p4[i1_11 >> 1];
                } else {
                    b00 = a00; b01 = a01; b10 = a10; b11 = a11;
                }

                bool q00p = (i0_00 & 1u), q01p = (i0_01 & 1u),
                     q10p = (i0_10 & 1u), q11p = (i0_11 & 1u);

                float2 e0_00 = q00p ? hi2(a00) : lo2(a00);
                float2 e0_01 = q01p ? hi2(a01) : lo2(a01);
                float2 e0_10 = q10p ? hi2(a10) : lo2(a10);
                float2 e0_11 = q11p ? hi2(a11) : lo2(a11);
                float2 e1_00 = q00p ? lo2(b00) : hi2(b00);
                float2 e1_01 = q01p ? lo2(b01) : hi2(b01);
                float2 e1_10 = q10p ? lo2(b10) : hi2(b10);
                float2 e1_11 = q11p ? lo2(b11) : hi2(b11);

                float2 t00 = lerp2(e0_00, e1_00, fx);
                float2 t01 = lerp2(e0_01, e1_01, fx);
                float2 t10 = lerp2(e0_10, e1_10, fx);
                float2 t11 = lerp2(e0_11, e1_11, fx);
                float2 u0 = lerp2(t00, t01, fz);
                float2 u1 = lerp2(t10, t11, fz);
                v = lerp2(u0, u1, fy);
            }

            sp[3 + 2 * l]     = v.x;
            sp[3 + 2 * l + 1] = v.y;
        }
    }
    srow[tid] = orig;

    __syncthreads();

    // warp-cooperative row writes, streaming (output is write-once)
    const int warp = tid >> 5;
    const int lane = tid & 31;
#pragma unroll 4
    for (int r = 0; r < 32; r++) {
        int p = warp * 32 + r;
        int row = srow[p];
        if (row >= 0) {
            const float* src = &s[p * 35];
            long long base = (long long)row * 35;
            __stcs(&out[base + lane], src[lane]);
            if (lane < 3) __stcs(&out[base + 32 + lane], src[32 + lane]);
        }
    }

    // re-zero g_hist for the next graph replay — moved OFF the critical-path
    // prologue to the kernel tail (scatter is complete at kernel start, and the
    // next replay's keyhist is stream-ordered after this kernel finishes;
    // __device__ globals start zeroed for the very first run)
    for (long long zi = j; zi < NB + 1; zi += (long long)gridDim.x * 256)
        g_hist[zi] = 0;
}

// ---------------- launch ----------------
static void launch_pdl(void* func, dim3 grid, dim3 block, void** args)
{
    cudaLaunchConfig_t cfg = {};
    cfg.gridDim = grid;
    cfg.blockDim = block;
    cfg.dynamicSmemBytes = 0;
    cfg.stream = 0;   // legacy stream (the one the harness captures)
    cudaLaunchAttribute attr[1];
    attr[0].id = cudaLaunchAttributeProgrammaticStreamSerialization;
    attr[0].val.programmaticStreamSerializationAllowed = 1;
    cfg.attrs = attr;
    cfg.numAttrs = 1;
    cudaLaunchKernelExC(&cfg, func, args);
}

extern "C" void kernel_launch(void* const* d_in, const int* in_sizes, int n_in,
                              void* d_out, int out_size)
{
    const float* xyz = (const float*)d_in[0];
    const float* emb = (const float*)d_in[1];
    float* out = (float*)d_out;
    const int B = in_sizes[0] / 3;
    const int nblk = (B + 255) / 256;      // hashgrid grid (1 pt/thread)
    const int nblk4 = (B + 1023) / 1024;   // keyhist/scatter grids (4 pts/thread)

    if (B > 0 && B <= MAXB) {
        keyhist_kernel<<<nblk4, 256>>>(xyz, B);

        launch_pdl((void*)scan_fused_kernel, dim3(NB / 1024), dim3(1024), nullptr);

        const float2* emb2 = (const float2*)emb;
        void* sargs[3] = { (void*)&xyz, (void*)&emb2, (void*)&B };
        launch_pdl((void*)scatter_build_kernel, dim3(nblk4 + NBLK_A), dim3(256), sargs);

        int one = 1;
        void* hargs[5] = { (void*)&xyz, (void*)&emb, (void*)&out, (void*)&B, (void*)&one };
        launch_pdl((void*)hashgrid_kernel, dim3(nblk), dim3(256), hargs);
    } else if (B > 0) {
        scatter_build_kernel<<<NBLK_A, 256>>>(xyz, (const float2*)emb, 0);
        hashgrid_kernel<<<nblk, 256>>>(xyz, emb, out, B, 0);
    }
}